// round 2
// baseline (speedup 1.0000x reference)
#include <cuda_runtime.h>
#include <cstdint>

// QuantumParity analytic reduction (see R1):
//   feat_k     = prod_{q=0..k}   cos(x_q)
//   feat_(i,j) = prod_{q=i+1..j} cos(x_q)
//   out[c] = b[c] + sum_f W[c][f] * feat_f
//
// R2: packed f32x2 math for the 2-channel dot (fma.rn.f32x2), W interleaved
// as float2 in shared (1 LDS.64 per feature), degree-9 cos poly, x loads
// hoisted above the smem prologue barrier.

#define NQ 8
#define NFEAT 36

__device__ __forceinline__ uint64_t pack_dup(float v) {
    uint64_t r;
    asm("mov.b64 %0, {%1, %1};" : "=l"(r) : "f"(v));
    return r;
}
__device__ __forceinline__ uint64_t fma2(uint64_t a, uint64_t b, uint64_t c) {
    uint64_t d;
    asm("fma.rn.f32x2 %0, %1, %2, %3;" : "=l"(d) : "l"(a), "l"(b), "l"(c));
    return d;
}
__device__ __forceinline__ uint64_t mul2(uint64_t a, uint64_t b) {
    uint64_t d;
    asm("mul.rn.f32x2 %0, %1, %2;" : "=l"(d) : "l"(a), "l"(b));
    return d;
}
__device__ __forceinline__ uint64_t lds64(uint32_t addr) {
    uint64_t d;
    asm("ld.shared.b64 %0, [%1];" : "=l"(d) : "r"(addr));
    return d;
}

__device__ __forceinline__ float cos_poly(float x) {
    // x in [0, pi]; cos(x) = -sin(x - pi/2). Degree-9 Taylor, |err| < 2.8e-6.
    float t = x - 1.57079632679489662f;
    float u = t * t;
    float p = fmaf(u, 2.75573192e-6f, -1.98412698e-4f);
    p = fmaf(u, p, 8.33333333e-3f);
    p = fmaf(u, p, -1.66666667e-1f);
    p = fmaf(u, p, 1.0f);
    return -t * p;
}

__global__ void __launch_bounds__(128)
quantum_parity_kernel(const float* __restrict__ x,
                      const float* __restrict__ W,
                      const float* __restrict__ bias,
                      float* __restrict__ out,
                      int nrows) {
    __shared__ float2 sW[NFEAT + 1];  // sW[f] = {W[0][f], W[1][f]}, sW[36] = bias
    int tid = threadIdx.x;
    int row = blockIdx.x * 128 + tid;
    int rl = row < nrows ? row : (nrows - 1);  // clamp so loads are always safe

    // Hoist input loads above the smem prologue: DRAM latency overlaps barrier.
    const float4* xp = reinterpret_cast<const float4*>(x) + (size_t)rl * 2;
    float4 a = xp[0];
    float4 d = xp[1];

    if (tid < NFEAT) sW[tid] = make_float2(W[tid], W[NFEAT + tid]);
    if (tid == NFEAT) sW[NFEAT] = make_float2(bias[0], bias[1]);
    __syncthreads();

    uint32_t sbase = (uint32_t)__cvta_generic_to_shared(sW);

    // 8 cosines (scalar), then duplicate each into both f32x2 lanes once.
    uint64_t cd[NQ];
    cd[0] = pack_dup(cos_poly(a.x));
    cd[1] = pack_dup(cos_poly(a.y));
    cd[2] = pack_dup(cos_poly(a.z));
    cd[3] = pack_dup(cos_poly(a.w));
    cd[4] = pack_dup(cos_poly(d.x));
    cd[5] = pack_dup(cos_poly(d.y));
    cd[6] = pack_dup(cos_poly(d.z));
    cd[7] = pack_dup(cos_poly(d.w));

    uint64_t acc = lds64(sbase + NFEAT * 8);  // bias pair

    // Single-Z features: prefix products, packed.
    uint64_t p = cd[0];
    acc = fma2(lds64(sbase + 0), p, acc);
#pragma unroll
    for (int k = 1; k < NQ; k++) {
        p = mul2(p, cd[k]);
        acc = fma2(lds64(sbase + k * 8), p, acc);
    }

    // Pair features: window products c_{i+1}..c_j, packed.
    int f = NQ;
#pragma unroll
    for (int i = 0; i < NQ - 1; i++) {
        uint64_t q = cd[i + 1];
        acc = fma2(lds64(sbase + f * 8), q, acc);
        f++;
#pragma unroll
        for (int j = i + 2; j < NQ; j++) {
            q = mul2(q, cd[j]);
            acc = fma2(lds64(sbase + f * 8), q, acc);
            f++;
        }
    }

    if (row < nrows)
        reinterpret_cast<uint64_t*>(out)[row] = acc;
}

extern "C" void kernel_launch(void* const* d_in, const int* in_sizes, int n_in,
                              void* d_out, int out_size) {
    const float* x    = (const float*)d_in[0];   // (B, 8) fp32
    const float* W    = (const float*)d_in[1];   // (2, 36) fp32
    const float* bias = (const float*)d_in[2];   // (2,) fp32

    int nrows = in_sizes[0] / NQ;                // 131072
    float* out = (float*)d_out;                  // (B, 2) fp32

    int block = 128;
    int grid = (nrows + block - 1) / block;
    quantum_parity_kernel<<<grid, block>>>(x, W, bias, out, nrows);
}

// round 3
// speedup vs baseline: 1.0435x; 1.0435x over previous
#include <cuda_runtime.h>
#include <cstdint>

// QuantumParity analytic reduction (see R1):
//   feat_k     = prod_{q=0..k}   cos(x_q)
//   feat_(i,j) = prod_{q=i+1..j} cos(x_q)
//   out[c] = b[c] + sum_f W[c][f] * feat_f
//
// R3: barrier moved BELOW the cosine computation so the cold W fetch overlaps
// per-warp x fetch + cos math; dot product split into 4 independent packed
// accumulator chains (RAW path 144 -> ~44 cyc).

#define NQ 8
#define NFEAT 36

__device__ __forceinline__ uint64_t pack_dup(float v) {
    uint64_t r;
    asm("mov.b64 %0, {%1, %1};" : "=l"(r) : "f"(v));
    return r;
}
__device__ __forceinline__ uint64_t fma2(uint64_t a, uint64_t b, uint64_t c) {
    uint64_t d;
    asm("fma.rn.f32x2 %0, %1, %2, %3;" : "=l"(d) : "l"(a), "l"(b), "l"(c));
    return d;
}
__device__ __forceinline__ uint64_t mul2(uint64_t a, uint64_t b) {
    uint64_t d;
    asm("mul.rn.f32x2 %0, %1, %2;" : "=l"(d) : "l"(a), "l"(b));
    return d;
}
__device__ __forceinline__ uint64_t add2(uint64_t a, uint64_t b) {
    uint64_t d;
    asm("add.rn.f32x2 %0, %1, %2;" : "=l"(d) : "l"(a), "l"(b));
    return d;
}
__device__ __forceinline__ uint64_t lds64(uint32_t addr) {
    uint64_t d;
    asm("ld.shared.b64 %0, [%1];" : "=l"(d) : "r"(addr));
    return d;
}

__device__ __forceinline__ float cos_poly(float x) {
    // x in [0, pi]; cos(x) = -sin(x - pi/2). Degree-9 Taylor, |err| < 2.8e-6.
    float t = x - 1.57079632679489662f;
    float u = t * t;
    float p = fmaf(u, 2.75573192e-6f, -1.98412698e-4f);
    p = fmaf(u, p, 8.33333333e-3f);
    p = fmaf(u, p, -1.66666667e-1f);
    p = fmaf(u, p, 1.0f);
    return -t * p;
}

__global__ void __launch_bounds__(256)
quantum_parity_kernel(const float* __restrict__ x,
                      const float* __restrict__ W,
                      const float* __restrict__ bias,
                      float* __restrict__ out,
                      int nrows) {
    __shared__ float2 sW[NFEAT + 1];  // sW[f] = {W[0][f], W[1][f]}, sW[36] = bias
    int tid = threadIdx.x;
    int row = blockIdx.x * 256 + tid;
    int rl = row < nrows ? row : (nrows - 1);  // clamp so loads are always safe

    // Issue the x load immediately (DRAM latency starts ticking).
    const float4* xp = reinterpret_cast<const float4*>(x) + (size_t)rl * 2;
    float4 a = xp[0];
    float4 d = xp[1];

    // W/bias fetch by the first 37 threads — in flight while everyone
    // computes cosines below. Barrier comes AFTER the cos math.
    if (tid <= NFEAT) {
        float lo, hi;
        if (tid < NFEAT) { lo = W[tid];  hi = W[NFEAT + tid]; }
        else             { lo = bias[0]; hi = bias[1]; }
        sW[tid] = make_float2(lo, hi);
    }

    // 8 cosines (scalar), duplicated once into both f32x2 lanes.
    uint64_t cd[NQ];
    cd[0] = pack_dup(cos_poly(a.x));
    cd[1] = pack_dup(cos_poly(a.y));
    cd[2] = pack_dup(cos_poly(a.z));
    cd[3] = pack_dup(cos_poly(a.w));
    cd[4] = pack_dup(cos_poly(d.x));
    cd[5] = pack_dup(cos_poly(d.y));
    cd[6] = pack_dup(cos_poly(d.z));
    cd[7] = pack_dup(cos_poly(d.w));

    __syncthreads();

    uint32_t sbase = (uint32_t)__cvta_generic_to_shared(sW);

    // 4 independent accumulator chains; features assigned round-robin.
    uint64_t acc[4];
    acc[0] = lds64(sbase + NFEAT * 8);  // bias pair
    acc[1] = 0;  // +0.0f == identity here (inputs are finite, no -0 concerns
    acc[2] = 0;  //  at 1e-3 tolerance)
    acc[3] = 0;

    int fc = 0;  // feature counter for round-robin chain assignment

    // Single-Z features: prefix products, packed.
    uint64_t p = cd[0];
    acc[fc & 3] = fma2(lds64(sbase + 0), p, acc[fc & 3]); fc++;
#pragma unroll
    for (int k = 1; k < NQ; k++) {
        p = mul2(p, cd[k]);
        acc[fc & 3] = fma2(lds64(sbase + k * 8), p, acc[fc & 3]); fc++;
    }

    // Pair features: window products c_{i+1}..c_j, packed.
    int f = NQ;
#pragma unroll
    for (int i = 0; i < NQ - 1; i++) {
        uint64_t q = cd[i + 1];
        acc[fc & 3] = fma2(lds64(sbase + f * 8), q, acc[fc & 3]); fc++; f++;
#pragma unroll
        for (int j = i + 2; j < NQ; j++) {
            q = mul2(q, cd[j]);
            acc[fc & 3] = fma2(lds64(sbase + f * 8), q, acc[fc & 3]); fc++; f++;
        }
    }

    uint64_t r = add2(add2(acc[0], acc[1]), add2(acc[2], acc[3]));

    if (row < nrows)
        reinterpret_cast<uint64_t*>(out)[row] = r;
}

extern "C" void kernel_launch(void* const* d_in, const int* in_sizes, int n_in,
                              void* d_out, int out_size) {
    const float* x    = (const float*)d_in[0];   // (B, 8) fp32
    const float* W    = (const float*)d_in[1];   // (2, 36) fp32
    const float* bias = (const float*)d_in[2];   // (2,) fp32

    int nrows = in_sizes[0] / NQ;                // 131072
    float* out = (float*)d_out;                  // (B, 2) fp32

    int block = 256;
    int grid = (nrows + block - 1) / block;
    quantum_parity_kernel<<<grid, block>>>(x, W, bias, out, nrows);
}